// round 3
// baseline (speedup 1.0000x reference)
#include <cuda_runtime.h>
#include <math.h>

#define K_CODES 1024
#define D_DIM   256
#define N_ROWS  131072

#define BM 128
#define BN 128
#define BD 32
#define NT 256

#define FLAG_THRESH  0.004f    // top-2 gap below this -> reference-emulation rescore
#define RESCUE_RPB   8         // flagged rows per rescue block

// Scratch (device globals: allocation-free per harness rules)
__device__ float        d_cnorm[K_CODES];   // emulated sum(e*e) per code
__device__ float        d_embedT[K_CODES * D_DIM];
__device__ unsigned int d_counts[K_CODES];
__device__ float        d_loss_partial[1024];
__device__ int          d_nflag;
__device__ int          d_flaglist[N_ROWS];

// ---------------------------------------------------------------------------
// Prep: emulated codebook norms (ascending-d, mul-then-add like jnp.sum(e*e)),
// transpose embed -> embedT [K][D], zero counts
// ---------------------------------------------------------------------------
__global__ void vq_prep(const float* __restrict__ embed) {
    int k = blockIdx.x * blockDim.x + threadIdx.x;  // 0..1023
    float s = 0.0f;
    for (int d = 0; d < D_DIM; ++d) {
        float v = embed[(size_t)d * K_CODES + k];   // coalesced over k
        s = __fadd_rn(s, __fmul_rn(v, v));          // rounded product, seq add
        d_embedT[(size_t)k * D_DIM + d] = v;
    }
    d_cnorm[k]  = s;
    d_counts[k] = 0u;
    if (k == 0) d_nflag = 0;
}

// ---------------------------------------------------------------------------
// Main: fused distance-GEMM + top2-argmin + gather + quantize + loss partials
// ---------------------------------------------------------------------------
__global__ void __launch_bounds__(NT, 1)
vq_main(const float* __restrict__ inputs,
        const float* __restrict__ embed,
        float* __restrict__ out) {
    extern __shared__ float smem[];
    float* As   = smem;                      // [256][128] d-major, XOR swizzled
    float* Bs   = As + D_DIM * BM;           // [32][128]
    int*   sIdx = (int*)(Bs + BD * BN);      // [128]
    float* sRed = (float*)(sIdx + BM);       // [8]

    const int t   = threadIdx.x;
    const int tx  = t & 15;
    const int ty  = t >> 4;
    const int row0 = blockIdx.x * BM;

    // ---- Load A block (128 rows x 256 d) transposed into smem ----
    {
        const float4* in4 = (const float4*)(inputs + (size_t)row0 * D_DIM);
        #pragma unroll
        for (int i = 0; i < 32; ++i) {
            int l  = i * NT + t;            // 0..8191
            int r  = l >> 6;                // row 0..127
            int d4 = l & 63;                // float4 index along d
            float4 v = in4[r * 64 + d4];
            int rs = r ^ ((d4 & 7) << 2);
            float* p = As + (4 * d4) * BM + rs;
            p[0 * BM] = v.x; p[1 * BM] = v.y; p[2 * BM] = v.z; p[3 * BM] = v.w;
        }
    }

    float rmin1[8], rmin2[8];
    int   ridx[8];
    #pragma unroll
    for (int i = 0; i < 8; ++i) { rmin1[i] = 3.4e38f; rmin2[i] = 3.4e38f; ridx[i] = 0; }

    float acc[8][8];

    for (int kc = 0; kc < K_CODES / BN; ++kc) {
        #pragma unroll
        for (int i = 0; i < 8; ++i)
            #pragma unroll
            for (int j = 0; j < 8; ++j) acc[i][j] = 0.0f;

        for (int dc = 0; dc < D_DIM / BD; ++dc) {
            __syncthreads();
            // load Bs chunk: embed[(dc*32+dl)*1024 + kc*128 + c]
            {
                const float4* e4 = (const float4*)(embed
                                     + (size_t)(dc * BD) * K_CODES + kc * BN);
                #pragma unroll
                for (int i = 0; i < 4; ++i) {
                    int l  = i * NT + t;        // 0..1023
                    int dl = l >> 5;
                    int c4 = l & 31;
                    float4 v = e4[dl * (K_CODES / 4) + c4];
                    *(float4*)(Bs + dl * BN + c4 * 4) = v;
                }
            }
            __syncthreads();

            #pragma unroll 8
            for (int d = 0; d < BD; ++d) {
                int dd  = dc * BD + d;
                int swz = ((dd >> 2) & 7) << 2;
                float a[8], b[8];
                float4 a0 = *(const float4*)(As + dd * BM + ((ty * 4) ^ swz));
                float4 a1 = *(const float4*)(As + dd * BM + (64 + ((ty * 4) ^ swz)));
                float4 b0 = *(const float4*)(Bs + d * BN + tx * 4);
                float4 b1 = *(const float4*)(Bs + d * BN + 64 + tx * 4);
                a[0]=a0.x; a[1]=a0.y; a[2]=a0.z; a[3]=a0.w;
                a[4]=a1.x; a[5]=a1.y; a[6]=a1.z; a[7]=a1.w;
                b[0]=b0.x; b[1]=b0.y; b[2]=b0.z; b[3]=b0.w;
                b[4]=b1.x; b[5]=b1.y; b[6]=b1.z; b[7]=b1.w;
                #pragma unroll
                for (int i = 0; i < 8; ++i)
                    #pragma unroll
                    for (int j = 0; j < 8; ++j)
                        acc[i][j] = fmaf(a[i], b[j], acc[i][j]);
            }
        }

        // ---- epilogue: dist = cnorm - 2*dot ; running top-2 argmin ----
        #pragma unroll
        for (int i = 0; i < 8; ++i) {
            float v1 = 3.4e38f, v2 = 3.4e38f; int i1 = 0;
            #pragma unroll
            for (int j = 0; j < 8; ++j) {
                int code = kc * BN + ((j < 4) ? (tx * 4 + j)
                                             : (64 + tx * 4 + (j - 4)));
                float dist = d_cnorm[code] - 2.0f * acc[i][j];
                if (dist < v1 || (dist == v1 && code < i1)) {
                    v2 = v1; v1 = dist; i1 = code;
                } else if (dist < v2) {
                    v2 = dist;
                }
            }
            // reduce across the 16 tx lanes (half-warp)
            #pragma unroll
            for (int off = 8; off; off >>= 1) {
                float w1 = __shfl_down_sync(0xffffffffu, v1, off, 16);
                int   wi = __shfl_down_sync(0xffffffffu, i1, off, 16);
                float w2 = __shfl_down_sync(0xffffffffu, v2, off, 16);
                if (w1 < v1 || (w1 == v1 && wi < i1)) {
                    v2 = fminf(v1, w2); v1 = w1; i1 = wi;
                } else {
                    v2 = fminf(v2, w1);
                }
            }
            if (tx == 0) {
                if (v1 < rmin1[i] || (v1 == rmin1[i] && i1 < ridx[i])) {
                    rmin2[i] = fminf(rmin1[i], v2);
                    rmin1[i] = v1; ridx[i] = i1;
                } else {
                    rmin2[i] = fminf(rmin2[i], v1);
                }
            }
        }
    }

    // ---- publish per-row indices; flag ambiguous rows ----
    if (tx == 0) {
        #pragma unroll
        for (int i = 0; i < 8; ++i) {
            int r = (i < 4) ? (ty * 4 + i) : (64 + ty * 4 + (i - 4));
            sIdx[r] = ridx[i];
            if (rmin2[i] - rmin1[i] < FLAG_THRESH) {
                int pos = atomicAdd(&d_nflag, 1);
                d_flaglist[pos] = row0 + r;
            }
        }
    }
    __syncthreads();

    const size_t ND = (size_t)N_ROWS * D_DIM;
    if (t < BM) {
        int k = sIdx[t];
        atomicAdd(&d_counts[k], 1u);
        out[ND + 2 + (size_t)(row0 + t)] = (float)k;   // embed_ind as float
    }

    // ---- quantize (= q exactly) + loss ----
    float lsum = 0.0f;
    const float4* inp4 = (const float4*)(inputs + (size_t)row0 * D_DIM);
    float4*       out4 = (float4*)(out + (size_t)row0 * D_DIM);
    const float4* eT4  = (const float4*)d_embedT;
    #pragma unroll 4
    for (int it = 0; it < 32; ++it) {
        int l  = it * NT + t;
        int r  = l >> 6;
        int d4 = l & 63;
        float4 x = inp4[r * 64 + d4];
        int    k = sIdx[r];
        float4 q = eT4[(size_t)k * 64 + d4];
        float dx = q.x - x.x, dy = q.y - x.y, dz = q.z - x.z, dw = q.w - x.w;
        lsum += dx * dx + dy * dy + dz * dz + dw * dw;
        out4[r * 64 + d4] = q;
    }
    #pragma unroll
    for (int off = 16; off; off >>= 1)
        lsum += __shfl_down_sync(0xffffffffu, lsum, off);
    if ((t & 31) == 0) sRed[t >> 5] = lsum;
    __syncthreads();
    if (t == 0) {
        float s = 0.0f;
        #pragma unroll
        for (int w = 0; w < 8; ++w) s += sRed[w];
        d_loss_partial[blockIdx.x] = s;
    }
}

// ---------------------------------------------------------------------------
// Rescue: re-decide flagged rows by EMULATING the reference's fp32 arithmetic:
//   dot  : ascending-d single-accumulator FMA (sgemm/Eigen semantics)
//   sx2  : ascending-d, rounded mul then add (constant per row)
//   se2  : precomputed the same way (d_cnorm)
//   dist : f32( f32(sx2 - 2*dot) + se2 )   [left-assoc like the jnp expression]
//   pick : lowest index on exact fp32 ties (jnp.argmin)
// ---------------------------------------------------------------------------
__global__ void __launch_bounds__(256)
vq_fix(const float* __restrict__ inputs, float* __restrict__ out) {
    __shared__ float sx[RESCUE_RPB][D_DIM];
    __shared__ float sdist[RESCUE_RPB][K_CODES];
    __shared__ float ssx2[RESCUE_RPB];
    __shared__ int   srow[RESCUE_RPB];
    __shared__ int   sbest[RESCUE_RPB];
    const int t = threadIdx.x;
    const size_t ND = (size_t)N_ROWS * D_DIM;

    const int nf = d_nflag;
    for (int base = blockIdx.x * RESCUE_RPB; base < nf;
         base += gridDim.x * RESCUE_RPB) {
        const int cnt = min(RESCUE_RPB, nf - base);
        __syncthreads();
        if (t < cnt) srow[t] = d_flaglist[base + t];
        __syncthreads();
        for (int r = 0; r < cnt; ++r)
            sx[r][t] = inputs[(size_t)srow[r] * D_DIM + t];
        __syncthreads();
        if (t < cnt) {
            float s = 0.0f;
            for (int d = 0; d < D_DIM; ++d)
                s = __fadd_rn(s, __fmul_rn(sx[t][d], sx[t][d]));
            ssx2[t] = s;
        }
        __syncthreads();

        // 256 threads x 4 codes; 8 rows share one codebook stream
        #pragma unroll
        for (int c = 0; c < 4; ++c) {
            const int k = c * 256 + t;
            const float* e = d_embedT + (size_t)k * D_DIM;
            float acc[RESCUE_RPB];
            #pragma unroll
            for (int r = 0; r < RESCUE_RPB; ++r) acc[r] = 0.0f;
            for (int d = 0; d < D_DIM; ++d) {
                float ev = e[d];
                #pragma unroll
                for (int r = 0; r < RESCUE_RPB; ++r)
                    acc[r] = __fmaf_rn(sx[r][d], ev, acc[r]);
            }
            #pragma unroll
            for (int r = 0; r < RESCUE_RPB; ++r) {
                float twod = __fadd_rn(acc[r], acc[r]);   // exact (x2)
                float t1   = __fsub_rn(ssx2[r], twod);
                sdist[r][k] = __fadd_rn(t1, d_cnorm[k]);
            }
        }
        __syncthreads();

        if (t < cnt) {
            float best = 3.4e38f; int bk = 0;
            for (int k = 0; k < K_CODES; ++k) {       // ascending, strict <
                float v = sdist[t][k];
                if (v < best) { best = v; bk = k; }
            }
            sbest[t] = bk;
            int oldk = (int)out[ND + 2 + (size_t)srow[t]];
            if (oldk != bk) {
                atomicAdd(&d_counts[bk], 1u);
                atomicAdd(&d_counts[oldk], 0xFFFFFFFFu);
                out[ND + 2 + (size_t)srow[t]] = (float)bk;
            }
        }
        __syncthreads();
        for (int r = 0; r < cnt; ++r)
            out[(size_t)srow[r] * D_DIM + t] =
                d_embedT[(size_t)sbest[r] * D_DIM + t];
    }
}

// ---------------------------------------------------------------------------
// Finalize: loss mean + perplexity (deterministic fixed-order reductions)
// ---------------------------------------------------------------------------
__global__ void vq_finalize(float* __restrict__ out) {
    __shared__ float sl[1024];
    __shared__ float se[1024];
    int t = threadIdx.x;
    sl[t] = d_loss_partial[t];
    float avg = (float)d_counts[t] * (1.0f / (float)N_ROWS);
    se[t] = avg * logf(avg + 1e-10f);
    __syncthreads();
    for (int s = 512; s; s >>= 1) {
        if (t < s) { sl[t] += sl[t + s]; se[t] += se[t + s]; }
        __syncthreads();
    }
    if (t == 0) {
        const size_t ND = (size_t)N_ROWS * D_DIM;
        out[ND]     = sl[0] / ((float)N_ROWS * (float)D_DIM);
        out[ND + 1] = expf(-se[0]);
    }
}

// ---------------------------------------------------------------------------
extern "C" void kernel_launch(void* const* d_in, const int* in_sizes, int n_in,
                              void* d_out, int out_size) {
    const float* inputs = (const float*)d_in[0];  // [131072, 256]
    const float* embed  = (const float*)d_in[1];  // [256, 1024]
    float* out = (float*)d_out;

    const int smem_bytes = (D_DIM * BM + BD * BN) * 4 + BM * 4 + 8 * 4;
    cudaFuncSetAttribute(vq_main, cudaFuncAttributeMaxDynamicSharedMemorySize,
                         smem_bytes);

    vq_prep<<<8, 128>>>(embed);
    vq_main<<<N_ROWS / BM, NT, smem_bytes>>>(inputs, embed, out);
    vq_fix<<<256, 256>>>(inputs, out);
    vq_finalize<<<1, 1024>>>(out);
}

// round 8
// speedup vs baseline: 1.3069x; 1.3069x over previous
#include <cuda_runtime.h>
#include <math.h>
#include <stdint.h>

#define K_CODES 1024
#define D_DIM   256
#define N_ROWS  131072

#define FLAG_THRESH  0.25f     // tf32 dist-error std ~0.02 -> ~12 sigma
#define RESCUE_RPB   8

// ---------------- scratch (device globals; no allocations allowed) ----------
__device__ float        d_cnorm[K_CODES];            // emulated sum(e*e)
__device__ float        d_embedT[K_CODES * D_DIM];   // fp32 codebook, k-major
__device__ unsigned int d_counts[K_CODES];
__device__ float        d_loss_partial[1024];
__device__ int          d_nflag;
__device__ int          d_flaglist[N_ROWS];

__device__ __forceinline__ uint32_t f2tf32(float f) {
    uint32_t r;
    asm("cvt.rna.tf32.f32 %0, %1;" : "=r"(r) : "f"(f));
    return r;
}

// ---------------------------------------------------------------------------
// Prep: emulated codebook norms (ascending-d, mul-then-add), fp32 transpose
// ---------------------------------------------------------------------------
__global__ void vq_prep(const float* __restrict__ embed) {
    int k = blockIdx.x * blockDim.x + threadIdx.x;  // 0..1023
    float s = 0.0f;
    for (int d = 0; d < D_DIM; ++d) {
        float v = embed[(size_t)d * K_CODES + k];
        s = __fadd_rn(s, __fmul_rn(v, v));
        d_embedT[(size_t)k * D_DIM + d] = v;
    }
    d_cnorm[k]  = s;
    d_counts[k] = 0u;
    if (k == 0) d_nflag = 0;
}

// ---------------------------------------------------------------------------
// SMEM layout (bytes):
//   [0,4096)        sCn   (1024 f32)
//   [4096,4608)     sIdx  (128 int)
//   [4608,4640)     sRed  (8 f32)
//   [4640,135712)   fragA (8 mtiles x 32 ksteps x 32 lanes x 4 regs, tf32)
//   [135712,168480) fragB (2 bufs x [4 ksl x 16 nt x 32 lanes x 2 regs]=4096u32)
// ---------------------------------------------------------------------------
#define SM_CN   0
#define SM_IDX  4096
#define SM_RED  4608
#define SM_A    4640
#define SM_B    135712
#define SMEM_TOTAL 168480
#define BSTRIDE 4096        // u32 per fragB buffer (FIX: was 8192 -> smem OOB)

__device__ __forceinline__ void mma_tf32(float c[4], uint32_t a0, uint32_t a1,
                                         uint32_t a2, uint32_t a3,
                                         uint32_t b0, uint32_t b1) {
    asm volatile(
        "mma.sync.aligned.m16n8k8.row.col.f32.tf32.tf32.f32 "
        "{%0,%1,%2,%3}, {%4,%5,%6,%7}, {%8,%9}, {%0,%1,%2,%3};"
        : "+f"(c[0]), "+f"(c[1]), "+f"(c[2]), "+f"(c[3])
        : "r"(a0), "r"(a1), "r"(a2), "r"(a3), "r"(b0), "r"(b1));
}

__device__ __forceinline__ void top2_upd(float& v1, float& v2, int& i1,
                                         float d, int code) {
    if (d < v1)      { v2 = v1; v1 = d; i1 = code; }
    else if (d < v2) { v2 = d; }
}

__global__ void __launch_bounds__(256, 1)
vq_main_mma(const float* __restrict__ inputs,
            const float* __restrict__ embed,
            float* __restrict__ out) {
    extern __shared__ char smem[];
    float*    sCn   = (float*)(smem + SM_CN);
    int*      sIdx  = (int*)(smem + SM_IDX);
    float*    sRed  = (float*)(smem + SM_RED);
    uint32_t* fragA = (uint32_t*)(smem + SM_A);
    uint32_t* fragB = (uint32_t*)(smem + SM_B);

    const int t    = threadIdx.x;
    const int wid  = t >> 5;
    const int lane = t & 31;
    const int row0 = blockIdx.x * 128;

    for (int i = t; i < K_CODES; i += 256) sCn[i] = d_cnorm[i];

    // ---- Stage A (128 rows x 256 d) -> fragment-major smem, tf32-rounded ---
    {
        const float4* in4 = (const float4*)(inputs + (size_t)row0 * D_DIM);
        #pragma unroll
        for (int i = 0; i < 32; ++i) {
            int l   = i * 256 + t;           // 0..8191
            int row = l >> 6;
            int d4  = l & 63;
            float4 v = in4[row * 64 + d4];
            int d   = d4 * 4;
            int mt  = row >> 4, r16 = row & 15;
            int reg = ((d & 4) ? 2 : 0) + ((r16 >= 8) ? 1 : 0);
            int ksg = d >> 3;
            uint32_t* p = fragA + ((mt * 32 + ksg) * 32 + (r16 & 7) * 4) * 4 + reg;
            p[0]  = f2tf32(v.x);
            p[4]  = f2tf32(v.y);
            p[8]  = f2tf32(v.z);
            p[12] = f2tf32(v.w);
        }
    }

    // ---- Prefetch + stage B chunk g=0 ----
    float4 pv[4];
    {
        const float4* src = (const float4*)(embed);   // kc=0, dchunk=0
        #pragma unroll
        for (int q = 0; q < 4; ++q) {
            int fi = q * 256 + t;
            pv[q] = src[(fi >> 5) * 256 + (fi & 31)];
        }
        #pragma unroll
        for (int q = 0; q < 4; ++q) {
            int fi = q * 256 + t;
            int d = fi >> 5, c4 = fi & 31;
            int code0 = c4 * 4;
            int ksl = d >> 3, c = d & 7, reg = c >> 2, cm = c & 3;
            int nt = code0 >> 3, cl0 = code0 & 7;
            uint32_t* b = fragB + ((ksl * 16 + nt) * 32) * 2 + cm * 2 + reg;
            b[(cl0 + 0) * 8] = f2tf32(pv[q].x);
            b[(cl0 + 1) * 8] = f2tf32(pv[q].y);
            b[(cl0 + 2) * 8] = f2tf32(pv[q].z);
            b[(cl0 + 3) * 8] = f2tf32(pv[q].w);
        }
    }
    __syncthreads();

    float acc[16][4];
    #pragma unroll
    for (int nt = 0; nt < 16; ++nt)
        #pragma unroll
        for (int r = 0; r < 4; ++r) acc[nt][r] = 0.0f;

    float v1a = 3.4e38f, v2a = 3.4e38f; int i1a = 0;   // row wid*16 + lane/4
    float v1b = 3.4e38f, v2b = 3.4e38f; int i1b = 0;   // +8

    const uint32_t* fA = fragA + (wid * 32) * 32 * 4 + lane * 4;

    for (int g = 0; g < 64; ++g) {          // g decomposes as kc=g>>3, dc=g&7
        // prefetch next B chunk
        if (g < 63) {
            int gn = g + 1;
            const float4* src = (const float4*)(embed
                + (size_t)((gn & 7) * 32) * K_CODES + (gn >> 3) * 128);
            #pragma unroll
            for (int q = 0; q < 4; ++q) {
                int fi = q * 256 + t;
                pv[q] = src[(fi >> 5) * 256 + (fi & 31)];
            }
        }

        // compute chunk g
        {
            const uint32_t* fB = fragB + (g & 1) * BSTRIDE + lane * 2;
            #pragma unroll
            for (int ks = 0; ks < 4; ++ks) {
                int ksg = (g & 7) * 4 + ks;
                uint4 a = *(const uint4*)(fA + ksg * 128);
                #pragma unroll
                for (int nt = 0; nt < 16; ++nt) {
                    uint2 b = *(const uint2*)(fB + (ks * 16 + nt) * 64);
                    mma_tf32(acc[nt], a.x, a.y, a.z, a.w, b.x, b.y);
                }
            }
        }

        // epilogue at end of each kc (8 chunks)
        if ((g & 7) == 7) {
            int kc = g >> 3;
            #pragma unroll
            for (int nt = 0; nt < 16; ++nt) {
                int code = kc * 128 + nt * 8 + (lane & 3) * 2;
                float c0 = sCn[code]     - 2.0f * acc[nt][0];
                float c1 = sCn[code + 1] - 2.0f * acc[nt][1];
                float c2 = sCn[code]     - 2.0f * acc[nt][2];
                float c3 = sCn[code + 1] - 2.0f * acc[nt][3];
                top2_upd(v1a, v2a, i1a, c0, code);
                top2_upd(v1a, v2a, i1a, c1, code + 1);
                top2_upd(v1b, v2b, i1b, c2, code);
                top2_upd(v1b, v2b, i1b, c3, code + 1);
                acc[nt][0] = acc[nt][1] = acc[nt][2] = acc[nt][3] = 0.0f;
            }
        }

        // store next B chunk into the other buffer
        if (g < 63) {
            uint32_t* dst = fragB + ((g + 1) & 1) * BSTRIDE;
            #pragma unroll
            for (int q = 0; q < 4; ++q) {
                int fi = q * 256 + t;
                int d = fi >> 5, c4 = fi & 31;
                int code0 = c4 * 4;
                int ksl = d >> 3, c = d & 7, reg = c >> 2, cm = c & 3;
                int nt = code0 >> 3, cl0 = code0 & 7;
                uint32_t* b = dst + ((ksl * 16 + nt) * 32) * 2 + cm * 2 + reg;
                b[(cl0 + 0) * 8] = f2tf32(pv[q].x);
                b[(cl0 + 1) * 8] = f2tf32(pv[q].y);
                b[(cl0 + 2) * 8] = f2tf32(pv[q].z);
                b[(cl0 + 3) * 8] = f2tf32(pv[q].w);
            }
        }
        __syncthreads();
    }

    // ---- merge top-2 across the 4 lanes sharing each row ----
    #pragma unroll
    for (int off = 1; off < 4; off <<= 1) {
        float w1 = __shfl_down_sync(0xffffffffu, v1a, off, 4);
        int   wi = __shfl_down_sync(0xffffffffu, i1a, off, 4);
        float w2 = __shfl_down_sync(0xffffffffu, v2a, off, 4);
        if (w1 < v1a || (w1 == v1a && wi < i1a)) {
            v2a = fminf(v1a, w2); v1a = w1; i1a = wi;
        } else v2a = fminf(v2a, w1);
        w1 = __shfl_down_sync(0xffffffffu, v1b, off, 4);
        wi = __shfl_down_sync(0xffffffffu, i1b, off, 4);
        w2 = __shfl_down_sync(0xffffffffu, v2b, off, 4);
        if (w1 < v1b || (w1 == v1b && wi < i1b)) {
            v2b = fminf(v1b, w2); v1b = w1; i1b = wi;
        } else v2b = fminf(v2b, w1);
    }

    const size_t ND = (size_t)N_ROWS * D_DIM;
    if ((lane & 3) == 0) {
        int rA = wid * 16 + (lane >> 2);
        int rB = rA + 8;
        sIdx[rA] = i1a;
        sIdx[rB] = i1b;
        if (v2a - v1a < FLAG_THRESH) {
            int pos = atomicAdd(&d_nflag, 1);
            d_flaglist[pos] = row0 + rA;
        }
        if (v2b - v1b < FLAG_THRESH) {
            int pos = atomicAdd(&d_nflag, 1);
            d_flaglist[pos] = row0 + rB;
        }
        atomicAdd(&d_counts[i1a], 1u);
        atomicAdd(&d_counts[i1b], 1u);
        out[ND + 2 + (size_t)(row0 + rA)] = (float)i1a;
        out[ND + 2 + (size_t)(row0 + rB)] = (float)i1b;
    }
    __syncthreads();

    // ---- quantize (= q exactly) + loss partials ----
    float lsum = 0.0f;
    const float4* inp4 = (const float4*)(inputs + (size_t)row0 * D_DIM);
    float4*       out4 = (float4*)(out + (size_t)row0 * D_DIM);
    const float4* eT4  = (const float4*)d_embedT;
    #pragma unroll 4
    for (int it = 0; it < 32; ++it) {
        int l  = it * 256 + t;
        int r  = l >> 6;
        int d4 = l & 63;
        float4 x = inp4[r * 64 + d4];
        int    k = sIdx[r];
        float4 q = eT4[(size_t)k * 64 + d4];
        float dx = q.x - x.x, dy = q.y - x.y, dz = q.z - x.z, dw = q.w - x.w;
        lsum += dx * dx + dy * dy + dz * dz + dw * dw;
        out4[r * 64 + d4] = q;
    }
    #pragma unroll
    for (int off = 16; off; off >>= 1)
        lsum += __shfl_down_sync(0xffffffffu, lsum, off);
    if ((t & 31) == 0) sRed[t >> 5] = lsum;
    __syncthreads();
    if (t == 0) {
        float s = 0.0f;
        #pragma unroll
        for (int w = 0; w < 8; ++w) s += sRed[w];
        d_loss_partial[blockIdx.x] = s;
    }
}

// ---------------------------------------------------------------------------
// Rescue: re-decide flagged rows with reference-emulated fp32 arithmetic
// ---------------------------------------------------------------------------
__global__ void __launch_bounds__(256)
vq_fix(const float* __restrict__ inputs, float* __restrict__ out) {
    __shared__ float sx[RESCUE_RPB][D_DIM];
    __shared__ float sdist[RESCUE_RPB][K_CODES];
    __shared__ float ssx2[RESCUE_RPB];
    __shared__ int   srow[RESCUE_RPB];
    __shared__ int   sbest[RESCUE_RPB];
    const int t = threadIdx.x;
    const size_t ND = (size_t)N_ROWS * D_DIM;

    const int nf = d_nflag;
    for (int base = blockIdx.x * RESCUE_RPB; base < nf;
         base += gridDim.x * RESCUE_RPB) {
        const int cnt = min(RESCUE_RPB, nf - base);
        __syncthreads();
        if (t < cnt) srow[t] = d_flaglist[base + t];
        __syncthreads();
        for (int r = 0; r < cnt; ++r)
            sx[r][t] = inputs[(size_t)srow[r] * D_DIM + t];
        __syncthreads();
        if (t < cnt) {
            float s = 0.0f;
            for (int d = 0; d < D_DIM; ++d)
                s = __fadd_rn(s, __fmul_rn(sx[t][d], sx[t][d]));
            ssx2[t] = s;
        }
        __syncthreads();

        #pragma unroll
        for (int c = 0; c < 4; ++c) {
            const int k = c * 256 + t;
            const float* e = d_embedT + (size_t)k * D_DIM;
            float acc[RESCUE_RPB];
            #pragma unroll
            for (int r = 0; r < RESCUE_RPB; ++r) acc[r] = 0.0f;
            for (int d = 0; d < D_DIM; ++d) {
                float ev = e[d];
                #pragma unroll
                for (int r = 0; r < RESCUE_RPB; ++r)
                    acc[r] = __fmaf_rn(sx[r][d], ev, acc[r]);
            }
            #pragma unroll
            for (int r = 0; r < RESCUE_RPB; ++r) {
                float twod = __fadd_rn(acc[r], acc[r]);
                float t1   = __fsub_rn(ssx2[r], twod);
                sdist[r][k] = __fadd_rn(t1, d_cnorm[k]);
            }
        }
        __syncthreads();

        if (t < cnt) {
            float best = 3.4e38f; int bk = 0;
            for (int k = 0; k < K_CODES; ++k) {
                float v = sdist[t][k];
                if (v < best) { best = v; bk = k; }
            }
            sbest[t] = bk;
            int oldk = (int)out[ND + 2 + (size_t)srow[t]];
            if (oldk != bk) {
                atomicAdd(&d_counts[bk], 1u);
                atomicAdd(&d_counts[oldk], 0xFFFFFFFFu);
                out[ND + 2 + (size_t)srow[t]] = (float)bk;
            }
        }
        __syncthreads();
        for (int r = 0; r < cnt; ++r)
            out[(size_t)srow[r] * D_DIM + t] =
                d_embedT[(size_t)sbest[r] * D_DIM + t];
    }
}

// ---------------------------------------------------------------------------
// Finalize: loss mean + perplexity
// ---------------------------------------------------------------------------
__global__ void vq_finalize(float* __restrict__ out) {
    __shared__ float sl[1024];
    __shared__ float se[1024];
    int t = threadIdx.x;
    sl[t] = d_loss_partial[t];
    float avg = (float)d_counts[t] * (1.0f / (float)N_ROWS);
    se[t] = avg * logf(avg + 1e-10f);
    __syncthreads();
    for (int s = 512; s; s >>= 1) {
        if (t < s) { sl[t] += sl[t + s]; se[t] += se[t + s]; }
        __syncthreads();
    }
    if (t == 0) {
        const size_t ND = (size_t)N_ROWS * D_DIM;
        out[ND]     = sl[0] / ((float)N_ROWS * (float)D_DIM);
        out[ND + 1] = expf(-se[0]);
    }
}

// ---------------------------------------------------------------------------
extern "C" void kernel_launch(void* const* d_in, const int* in_sizes, int n_in,
                              void* d_out, int out_size) {
    const float* inputs = (const float*)d_in[0];  // [131072, 256]
    const float* embed  = (const float*)d_in[1];  // [256, 1024]
    float* out = (float*)d_out;

    cudaFuncSetAttribute(vq_main_mma,
                         cudaFuncAttributeMaxDynamicSharedMemorySize,
                         SMEM_TOTAL);

    vq_prep<<<8, 128>>>(embed);
    vq_main_mma<<<N_ROWS / 128, 256, SMEM_TOTAL>>>(inputs, embed, out);
    vq_fix<<<256, 256>>>(inputs, out);
    vq_finalize<<<1, 1024>>>(out);
}

// round 9
// speedup vs baseline: 1.6174x; 1.2375x over previous
#include <cuda_runtime.h>
#include <cuda_bf16.h>
#include <math.h>
#include <stdint.h>

#define K_CODES 1024
#define D_DIM   256
#define N_ROWS  131072

#define FLAG_THRESH  0.65f     // bf16 dist-err std ~0.07 -> ~6.5 sigma on diff
#define RESCUE_RPB   8

// ---------------- scratch (device globals; no allocations allowed) ----------
__device__ float        d_cnorm[K_CODES];            // emulated sum(e*e)
__device__ float        d_embedT[K_CODES * D_DIM];   // fp32 codebook, k-major
__device__ uint32_t     d_eBfrag[64 * 2048];         // preformatted B fragments
__device__ unsigned int d_counts[K_CODES];
__device__ float        d_loss_partial[1024];
__device__ int          d_nflag;
__device__ int          d_flaglist[N_ROWS];

__device__ __forceinline__ uint32_t pack_bf2(float a, float b) {
    __nv_bfloat16 ha = __float2bfloat16_rn(a), hb = __float2bfloat16_rn(b);
    return (uint32_t)__bfloat16_as_ushort(ha) |
           ((uint32_t)__bfloat16_as_ushort(hb) << 16);
}

// ---------------------------------------------------------------------------
// Prep 1: emulated codebook norms (ascending-d, mul-then-add), fp32 transpose
// ---------------------------------------------------------------------------
__global__ void vq_prep(const float* __restrict__ embed) {
    int k = blockIdx.x * blockDim.x + threadIdx.x;  // 0..1023
    float s = 0.0f;
    for (int d = 0; d < D_DIM; ++d) {
        float v = embed[(size_t)d * K_CODES + k];
        s = __fadd_rn(s, __fmul_rn(v, v));
        d_embedT[(size_t)k * D_DIM + d] = v;
    }
    d_cnorm[k]  = s;
    d_counts[k] = 0u;
    if (k == 0) d_nflag = 0;
}

// ---------------------------------------------------------------------------
// Prep 2: build bf16 B fragments for mma.m16n8k16 (chunk-linear layout)
//   chunk g = kc*8 + dc  (kc: 128-code block, dc: 32-d block)
//   entry (ks, nt, lane): b0 = bf16x2(E[db+2t][c], E[db+2t+1][c])
//                         b1 = bf16x2(E[db+2t+8][c], E[db+2t+9][c])
//   db = dc*32 + ks*16, t = lane&3, c = kc*128 + nt*8 + (lane>>2)
// ---------------------------------------------------------------------------
__global__ void vq_prep_frag(const float* __restrict__ embed) {
    const int g = blockIdx.x;          // 0..63
    const int kc = g >> 3, dc = g & 7;
    #pragma unroll
    for (int q = 0; q < 4; ++q) {
        int e    = q * 256 + threadIdx.x;   // 0..1023
        int ks   = e >> 9;
        int nt   = (e >> 5) & 15;
        int lane = e & 31;
        int t4   = lane & 3;
        int gq   = lane >> 2;
        int code = kc * 128 + nt * 8 + gq;
        int db   = dc * 32 + ks * 16;
        float e0 = embed[(size_t)(db + 2*t4)     * K_CODES + code];
        float e1 = embed[(size_t)(db + 2*t4 + 1) * K_CODES + code];
        float e2 = embed[(size_t)(db + 2*t4 + 8) * K_CODES + code];
        float e3 = embed[(size_t)(db + 2*t4 + 9) * K_CODES + code];
        uint32_t* dst = d_eBfrag + ((size_t)g * 2048) + (size_t)e * 2;
        dst[0] = pack_bf2(e0, e1);
        dst[1] = pack_bf2(e2, e3);
    }
}

// ---------------------------------------------------------------------------
// SMEM layout (bytes):
//   [0,4096)       sCn   (1024 f32)
//   [4096,4608)    sIdx  (128 int)
//   [4608,4640)    sRed  (8 f32)
//   [4640,70176)   fragA (8 mt x 16 kstep16 x 32 lanes x 4 regs, bf16x2)
//   [70176,86560)  fragB (2 bufs x 2048 u32)
// ---------------------------------------------------------------------------
#define SM_CN   0
#define SM_IDX  4096
#define SM_RED  4608
#define SM_A    4640
#define SM_B    70176
#define SMEM_TOTAL 86560
#define BSTRIDE 2048        // u32 per fragB buffer

__device__ __forceinline__ void mma_bf16(float c[4], uint32_t a0, uint32_t a1,
                                         uint32_t a2, uint32_t a3,
                                         uint32_t b0, uint32_t b1) {
    asm volatile(
        "mma.sync.aligned.m16n8k16.row.col.f32.bf16.bf16.f32 "
        "{%0,%1,%2,%3}, {%4,%5,%6,%7}, {%8,%9}, {%0,%1,%2,%3};"
        : "+f"(c[0]), "+f"(c[1]), "+f"(c[2]), "+f"(c[3])
        : "r"(a0), "r"(a1), "r"(a2), "r"(a3), "r"(b0), "r"(b1));
}

__device__ __forceinline__ void top2_upd(float& v1, float& v2, int& i1,
                                         float d, int code) {
    if (d < v1)      { v2 = v1; v1 = d; i1 = code; }
    else if (d < v2) { v2 = d; }
}

__global__ void __launch_bounds__(256, 1)
vq_main_mma(const float* __restrict__ inputs, float* __restrict__ out) {
    extern __shared__ char smem[];
    float*    sCn   = (float*)(smem + SM_CN);
    int*      sIdx  = (int*)(smem + SM_IDX);
    float*    sRed  = (float*)(smem + SM_RED);
    uint32_t* fragA = (uint32_t*)(smem + SM_A);
    uint32_t* fragB = (uint32_t*)(smem + SM_B);

    const int t    = threadIdx.x;
    const int wid  = t >> 5;
    const int lane = t & 31;
    const int row0 = blockIdx.x * 128;

    for (int i = t; i < K_CODES; i += 256) sCn[i] = d_cnorm[i];

    // ---- Stage A (128 rows x 256 d) -> bf16 fragment-major smem ----
    // fragA[((mt*16 + kstep16)*32 + (r16&7)*4 + t4)*4 + reg]
    {
        const float4* in4 = (const float4*)(inputs + (size_t)row0 * D_DIM);
        #pragma unroll
        for (int i = 0; i < 32; ++i) {
            int l   = i * 256 + t;           // 0..8191
            int row = l >> 6;
            int d4  = l & 63;
            float4 v = in4[row * 64 + d4];
            int d   = d4 * 4;
            int mt  = row >> 4, r16 = row & 15;
            int ks16 = d >> 4;               // k16 step 0..15
            int o    = d & 15;
            int reg  = ((o & 8) ? 2 : 0) + ((r16 >= 8) ? 1 : 0);
            int t0   = (o & 7) >> 1;         // thread-in-group for (v.x,v.y)
            uint32_t* p = fragA + ((mt * 16 + ks16) * 32 + (r16 & 7) * 4 + t0) * 4 + reg;
            p[0] = pack_bf2(v.x, v.y);
            p[4] = pack_bf2(v.z, v.w);       // t0+1 -> +4 u32
        }
    }

    // ---- Prefetch + stage B chunk g=0 (pure copy, conflict-free) ----
    uint4 pv0, pv1;
    {
        const uint4* src = (const uint4*)d_eBfrag;
        pv0 = src[t];
        pv1 = src[t + 256];
        uint4* dst = (uint4*)fragB;
        dst[t]       = pv0;
        dst[t + 256] = pv1;
    }
    __syncthreads();

    float acc[16][4];
    #pragma unroll
    for (int nt = 0; nt < 16; ++nt)
        #pragma unroll
        for (int r = 0; r < 4; ++r) acc[nt][r] = 0.0f;

    float v1a = 3.4e38f, v2a = 3.4e38f; int i1a = 0;   // row wid*16 + lane/4
    float v1b = 3.4e38f, v2b = 3.4e38f; int i1b = 0;   // +8

    const uint32_t* fA = fragA + wid * 2048 + lane * 4;

    for (int g = 0; g < 64; ++g) {          // g = kc*8 + dc
        // prefetch next B chunk (linear copy from preformatted gmem)
        if (g < 63) {
            const uint4* src = (const uint4*)(d_eBfrag + (size_t)(g + 1) * 2048);
            pv0 = src[t];
            pv1 = src[t + 256];
        }

        // compute chunk g: 2 k16-steps x 16 n-tiles
        {
            const uint32_t* fB = fragB + (g & 1) * BSTRIDE + lane * 2;
            #pragma unroll
            for (int ks = 0; ks < 2; ++ks) {
                int ks16 = (g & 7) * 2 + ks;
                uint4 a = *(const uint4*)(fA + ks16 * 128);
                #pragma unroll
                for (int nt = 0; nt < 16; ++nt) {
                    uint2 b = *(const uint2*)(fB + (ks * 16 + nt) * 64);
                    mma_bf16(acc[nt], a.x, a.y, a.z, a.w, b.x, b.y);
                }
            }
        }

        // epilogue at end of each kc (8 chunks)
        if ((g & 7) == 7) {
            int kc = g >> 3;
            #pragma unroll
            for (int nt = 0; nt < 16; ++nt) {
                int code = kc * 128 + nt * 8 + (lane & 3) * 2;
                float c0 = sCn[code]     - 2.0f * acc[nt][0];
                float c1 = sCn[code + 1] - 2.0f * acc[nt][1];
                float c2 = sCn[code]     - 2.0f * acc[nt][2];
                float c3 = sCn[code + 1] - 2.0f * acc[nt][3];
                top2_upd(v1a, v2a, i1a, c0, code);
                top2_upd(v1a, v2a, i1a, c1, code + 1);
                top2_upd(v1b, v2b, i1b, c2, code);
                top2_upd(v1b, v2b, i1b, c3, code + 1);
                acc[nt][0] = acc[nt][1] = acc[nt][2] = acc[nt][3] = 0.0f;
            }
        }

        // store next B chunk into the other buffer
        if (g < 63) {
            uint4* dst = (uint4*)(fragB + ((g + 1) & 1) * BSTRIDE);
            dst[t]       = pv0;
            dst[t + 256] = pv1;
        }
        __syncthreads();
    }

    // ---- merge top-2 across the 4 lanes sharing each row ----
    #pragma unroll
    for (int off = 1; off < 4; off <<= 1) {
        float w1 = __shfl_down_sync(0xffffffffu, v1a, off, 4);
        int   wi = __shfl_down_sync(0xffffffffu, i1a, off, 4);
        float w2 = __shfl_down_sync(0xffffffffu, v2a, off, 4);
        if (w1 < v1a || (w1 == v1a && wi < i1a)) {
            v2a = fminf(v1a, w2); v1a = w1; i1a = wi;
        } else v2a = fminf(v2a, w1);
        w1 = __shfl_down_sync(0xffffffffu, v1b, off, 4);
        wi = __shfl_down_sync(0xffffffffu, i1b, off, 4);
        w2 = __shfl_down_sync(0xffffffffu, v2b, off, 4);
        if (w1 < v1b || (w1 == v1b && wi < i1b)) {
            v2b = fminf(v1b, w2); v1b = w1; i1b = wi;
        } else v2b = fminf(v2b, w1);
    }

    const size_t ND = (size_t)N_ROWS * D_DIM;
    if ((lane & 3) == 0) {
        int rA = wid * 16 + (lane >> 2);
        int rB = rA + 8;
        sIdx[rA] = i1a;
        sIdx[rB] = i1b;
        if (v2a - v1a < FLAG_THRESH) {
            int pos = atomicAdd(&d_nflag, 1);
            d_flaglist[pos] = row0 + rA;
        }
        if (v2b - v1b < FLAG_THRESH) {
            int pos = atomicAdd(&d_nflag, 1);
            d_flaglist[pos] = row0 + rB;
        }
        atomicAdd(&d_counts[i1a], 1u);
        atomicAdd(&d_counts[i1b], 1u);
        out[ND + 2 + (size_t)(row0 + rA)] = (float)i1a;
        out[ND + 2 + (size_t)(row0 + rB)] = (float)i1b;
    }
    __syncthreads();

    // ---- quantize (= q exactly) + loss partials ----
    float lsum = 0.0f;
    const float4* inp4 = (const float4*)(inputs + (size_t)row0 * D_DIM);
    float4*       out4 = (float4*)(out + (size_t)row0 * D_DIM);
    const float4* eT4  = (const float4*)d_embedT;
    #pragma unroll 4
    for (int it = 0; it < 32; ++it) {
        int l  = it * 256 + t;
        int r  = l >> 6;
        int d4 = l & 63;
        float4 x = inp4[r * 64 + d4];
        int    k = sIdx[r];
        float4 q = eT4[(size_t)k * 64 + d4];
        float dx = q.x - x.x, dy = q.y - x.y, dz = q.z - x.z, dw = q.w - x.w;
        lsum += dx * dx + dy * dy + dz * dz + dw * dw;
        out4[r * 64 + d4] = q;
    }
    #pragma unroll
    for (int off = 16; off; off >>= 1)
        lsum += __shfl_down_sync(0xffffffffu, lsum, off);
    if ((t & 31) == 0) sRed[t >> 5] = lsum;
    __syncthreads();
    if (t == 0) {
        float s = 0.0f;
        #pragma unroll
        for (int w = 0; w < 8; ++w) s += sRed[w];
        d_loss_partial[blockIdx.x] = s;
    }
}

// ---------------------------------------------------------------------------
// Rescue: re-decide flagged rows with reference-emulated fp32 arithmetic
// ---------------------------------------------------------------------------
__global__ void __launch_bounds__(256)
vq_fix(const float* __restrict__ inputs, float* __restrict__ out) {
    __shared__ float sx[RESCUE_RPB][D_DIM];
    __shared__ float sdist[RESCUE_RPB][K_CODES];
    __shared__ float ssx2[RESCUE_RPB];
    __shared__ int   srow[RESCUE_RPB];
    __shared__ int   sbest[RESCUE_RPB];
    const int t = threadIdx.x;
    const size_t ND = (size_t)N_ROWS * D_DIM;

    const int nf = d_nflag;
    for (int base = blockIdx.x * RESCUE_RPB; base < nf;
         base += gridDim.x * RESCUE_RPB) {
        const int cnt = min(RESCUE_RPB, nf - base);
        __syncthreads();
        if (t < cnt) srow[t] = d_flaglist[base + t];
        __syncthreads();
        for (int r = 0; r < cnt; ++r)
            sx[r][t] = inputs[(size_t)srow[r] * D_DIM + t];
        __syncthreads();
        if (t < cnt) {
            float s = 0.0f;
            for (int d = 0; d < D_DIM; ++d)
                s = __fadd_rn(s, __fmul_rn(sx[t][d], sx[t][d]));
            ssx2[t] = s;
        }
        __syncthreads();

        #pragma unroll
        for (int c = 0; c < 4; ++c) {
            const int k = c * 256 + t;
            const float* e = d_embedT + (size_t)k * D_DIM;
            float acc[RESCUE_RPB];
            #pragma unroll
            for (int r = 0; r < RESCUE_RPB; ++r) acc[r] = 0.0f;
            for (int d = 0; d < D_DIM; ++d) {
                float ev = e[d];
                #pragma unroll
                for (int r = 0; r < RESCUE_RPB; ++r)
                    acc[r] = __fmaf_rn(sx[r][d], ev, acc[r]);
            }
            #pragma unroll
            for (int r = 0; r < RESCUE_RPB; ++r) {
                float twod = __fadd_rn(acc[r], acc[r]);
                float t1   = __fsub_rn(ssx2[r], twod);
                sdist[r][k] = __fadd_rn(t1, d_cnorm[k]);
            }
        }
        __syncthreads();

        if (t < cnt) {
            float best = 3.4e38f; int bk = 0;
            for (int k = 0; k < K_CODES; ++k) {
                float v = sdist[t][k];
                if (v < best) { best = v; bk = k; }
            }
            sbest[t] = bk;
            int oldk = (int)out[ND + 2 + (size_t)srow[t]];
            if (oldk != bk) {
                atomicAdd(&d_counts[bk], 1u);
                atomicAdd(&d_counts[oldk], 0xFFFFFFFFu);
                out[ND + 2 + (size_t)srow[t]] = (float)bk;
            }
        }
        __syncthreads();
        for (int r = 0; r < cnt; ++r)
            out[(size_t)srow[r] * D_DIM + t] =
                d_embedT[(size_t)sbest[r] * D_DIM + t];
    }
}

// ---------------------------------------------------------------------------
// Finalize: loss mean + perplexity
// ---------------------------------------------------------------------------
__global__ void vq_finalize(float* __restrict__ out) {
    __shared__ float sl[1024];
    __shared__ float se[1024];
    int t = threadIdx.x;
    sl[t] = d_loss_partial[t];
    float avg = (float)d_counts[t] * (1.0f / (float)N_ROWS);
    se[t] = avg * logf(avg + 1e-10f);
    __syncthreads();
    for (int s = 512; s; s >>= 1) {
        if (t < s) { sl[t] += sl[t + s]; se[t] += se[t + s]; }
        __syncthreads();
    }
    if (t == 0) {
        const size_t ND = (size_t)N_ROWS * D_DIM;
        out[ND]     = sl[0] / ((float)N_ROWS * (float)D_DIM);
        out[ND + 1] = expf(-se[0]);
    }
}

// ---------------------------------------------------------------------------
extern "C" void kernel_launch(void* const* d_in, const int* in_sizes, int n_in,
                              void* d_out, int out_size) {
    const float* inputs = (const float*)d_in[0];  // [131072, 256]
    const float* embed  = (const float*)d_in[1];  // [256, 1024]
    float* out = (float*)d_out;

    cudaFuncSetAttribute(vq_main_mma,
                         cudaFuncAttributeMaxDynamicSharedMemorySize,
                         SMEM_TOTAL);

    vq_prep<<<8, 128>>>(embed);
    vq_prep_frag<<<64, 256>>>(embed);
    vq_main_mma<<<N_ROWS / 128, 256, SMEM_TOTAL>>>(inputs, out);
    vq_fix<<<256, 256>>>(inputs, out);
    vq_finalize<<<1, 1024>>>(out);
}

// round 10
// speedup vs baseline: 1.7567x; 1.0862x over previous
#include <cuda_runtime.h>
#include <cuda_bf16.h>
#include <math.h>
#include <stdint.h>

#define K_CODES 1024
#define D_DIM   256
#define N_ROWS  131072

#define FLAG_THRESH  0.65f     // bf16 dist-err std ~0.07 -> ~6.5 sigma on diff
#define RESCUE_RPB   8

// ---------------- scratch (device globals; no allocations allowed) ----------
__device__ float        d_cnorm[K_CODES];            // emulated sum(e*e)
__device__ float        d_embedT[K_CODES * D_DIM];   // fp32 codebook, k-major
__device__ uint32_t     d_eBfrag[64 * 2048];         // preformatted B fragments
__device__ unsigned int d_counts[K_CODES];
__device__ float        d_loss_partial[1024];
__device__ int          d_nflag;
__device__ int          d_flaglist[N_ROWS];

__device__ __forceinline__ uint32_t pack_bf2(float a, float b) {
    __nv_bfloat16 ha = __float2bfloat16_rn(a), hb = __float2bfloat16_rn(b);
    return (uint32_t)__bfloat16_as_ushort(ha) |
           ((uint32_t)__bfloat16_as_ushort(hb) << 16);
}

// ---------------------------------------------------------------------------
// Prep 1: emulated codebook norms (ascending-d, mul-then-add), fp32 transpose
// ---------------------------------------------------------------------------
__global__ void vq_prep(const float* __restrict__ embed) {
    int k = blockIdx.x * blockDim.x + threadIdx.x;  // 0..1023
    float s = 0.0f;
    for (int d = 0; d < D_DIM; ++d) {
        float v = embed[(size_t)d * K_CODES + k];
        s = __fadd_rn(s, __fmul_rn(v, v));
        d_embedT[(size_t)k * D_DIM + d] = v;
    }
    d_cnorm[k]  = s;
    d_counts[k] = 0u;
    if (k == 0) d_nflag = 0;
}

// ---------------------------------------------------------------------------
// Prep 2: build bf16 B fragments for mma.m16n8k16 (chunk-linear layout)
// ---------------------------------------------------------------------------
__global__ void vq_prep_frag(const float* __restrict__ embed) {
    const int g = blockIdx.x;          // 0..63
    const int kc = g >> 3, dc = g & 7;
    #pragma unroll
    for (int q = 0; q < 4; ++q) {
        int e    = q * 256 + threadIdx.x;   // 0..1023
        int ks   = e >> 9;
        int nt   = (e >> 5) & 15;
        int lane = e & 31;
        int t4   = lane & 3;
        int gq   = lane >> 2;
        int code = kc * 128 + nt * 8 + gq;
        int db   = dc * 32 + ks * 16;
        float e0 = embed[(size_t)(db + 2*t4)     * K_CODES + code];
        float e1 = embed[(size_t)(db + 2*t4 + 1) * K_CODES + code];
        float e2 = embed[(size_t)(db + 2*t4 + 8) * K_CODES + code];
        float e3 = embed[(size_t)(db + 2*t4 + 9) * K_CODES + code];
        uint32_t* dst = d_eBfrag + ((size_t)g * 2048) + (size_t)e * 2;
        dst[0] = pack_bf2(e0, e1);
        dst[1] = pack_bf2(e2, e3);
    }
}

// ---------------------------------------------------------------------------
// SMEM layout (bytes):
//   [0,4096)       sCn   (1024 f32)
//   [4096,4608)    sIdx  (128 int)
//   [4608,4640)    sRed  (8 f32)
//   [4640,70176)   fragA (8 mt x 16 kstep16 x 32 lanes x 4 regs, bf16x2)
//   [70176,86560)  fragB (2 bufs x 2048 u32)
// 86.5KB/CTA -> 2 CTAs/SM (173KB of 227KB)
// ---------------------------------------------------------------------------
#define SM_CN   0
#define SM_IDX  4096
#define SM_RED  4608
#define SM_A    4640
#define SM_B    70176
#define SMEM_TOTAL 86560
#define BSTRIDE 2048        // u32 per fragB buffer

__device__ __forceinline__ void mma_bf16(float c[4], uint32_t a0, uint32_t a1,
                                         uint32_t a2, uint32_t a3,
                                         uint32_t b0, uint32_t b1) {
    asm volatile(
        "mma.sync.aligned.m16n8k16.row.col.f32.bf16.bf16.f32 "
        "{%0,%1,%2,%3}, {%4,%5,%6,%7}, {%8,%9}, {%0,%1,%2,%3};"
        : "+f"(c[0]), "+f"(c[1]), "+f"(c[2]), "+f"(c[3])
        : "r"(a0), "r"(a1), "r"(a2), "r"(a3), "r"(b0), "r"(b1));
}

__device__ __forceinline__ void top2_upd(float& v1, float& v2, int& i1,
                                         float d, int code) {
    if (d < v1)      { v2 = v1; v1 = d; i1 = code; }
    else if (d < v2) { v2 = d; }
}

__global__ void __launch_bounds__(256, 2)
vq_main_mma(const float* __restrict__ inputs, float* __restrict__ out) {
    extern __shared__ char smem[];
    float*    sCn   = (float*)(smem + SM_CN);
    int*      sIdx  = (int*)(smem + SM_IDX);
    float*    sRed  = (float*)(smem + SM_RED);
    uint32_t* fragA = (uint32_t*)(smem + SM_A);
    uint32_t* fragB = (uint32_t*)(smem + SM_B);

    const int t    = threadIdx.x;
    const int wid  = t >> 5;
    const int lane = t & 31;
    const int row0 = blockIdx.x * 128;

    for (int i = t; i < K_CODES; i += 256) sCn[i] = d_cnorm[i];

    // ---- Stage A (128 rows x 256 d) -> bf16 fragment-major smem ----
    {
        const float4* in4 = (const float4*)(inputs + (size_t)row0 * D_DIM);
        #pragma unroll
        for (int i = 0; i < 32; ++i) {
            int l   = i * 256 + t;           // 0..8191
            int row = l >> 6;
            int d4  = l & 63;
            float4 v = in4[row * 64 + d4];
            int d   = d4 * 4;
            int mt  = row >> 4, r16 = row & 15;
            int ks16 = d >> 4;               // k16 step 0..15
            int o    = d & 15;
            int reg  = ((o & 8) ? 2 : 0) + ((r16 >= 8) ? 1 : 0);
            int t0   = (o & 7) >> 1;         // thread-in-group for (v.x,v.y)
            uint32_t* p = fragA + ((mt * 16 + ks16) * 32 + (r16 & 7) * 4 + t0) * 4 + reg;
            p[0] = pack_bf2(v.x, v.y);
            p[4] = pack_bf2(v.z, v.w);       // t0+1 -> +4 u32
        }
    }

    // ---- Prefetch + stage B chunk g=0 (pure copy, conflict-free) ----
    uint4 pv0, pv1;
    {
        const uint4* src = (const uint4*)d_eBfrag;
        pv0 = src[t];
        pv1 = src[t + 256];
        uint4* dst = (uint4*)fragB;
        dst[t]       = pv0;
        dst[t + 256] = pv1;
    }
    __syncthreads();

    float acc[16][4];
    #pragma unroll
    for (int nt = 0; nt < 16; ++nt)
        #pragma unroll
        for (int r = 0; r < 4; ++r) acc[nt][r] = 0.0f;

    float v1a = 3.4e38f, v2a = 3.4e38f; int i1a = 0;   // row wid*16 + lane/4
    float v1b = 3.4e38f, v2b = 3.4e38f; int i1b = 0;   // +8

    const uint32_t* fA = fragA + wid * 2048 + lane * 4;

    for (int g = 0; g < 64; ++g) {          // g = kc*8 + dc
        // prefetch next B chunk (linear copy from preformatted gmem)
        if (g < 63) {
            const uint4* src = (const uint4*)(d_eBfrag + (size_t)(g + 1) * 2048);
            pv0 = src[t];
            pv1 = src[t + 256];
        }

        // compute chunk g: 2 k16-steps x 16 n-tiles
        {
            const uint32_t* fB = fragB + (g & 1) * BSTRIDE + lane * 2;
            #pragma unroll
            for (int ks = 0; ks < 2; ++ks) {
                int ks16 = (g & 7) * 2 + ks;
                uint4 a = *(const uint4*)(fA + ks16 * 128);
                #pragma unroll
                for (int nt = 0; nt < 16; ++nt) {
                    uint2 b = *(const uint2*)(fB + (ks * 16 + nt) * 64);
                    mma_bf16(acc[nt], a.x, a.y, a.z, a.w, b.x, b.y);
                }
            }
        }

        // epilogue at end of each kc (8 chunks)
        if ((g & 7) == 7) {
            int kc = g >> 3;
            #pragma unroll
            for (int nt = 0; nt < 16; ++nt) {
                int code = kc * 128 + nt * 8 + (lane & 3) * 2;
                float c0 = sCn[code]     - 2.0f * acc[nt][0];
                float c1 = sCn[code + 1] - 2.0f * acc[nt][1];
                float c2 = sCn[code]     - 2.0f * acc[nt][2];
                float c3 = sCn[code + 1] - 2.0f * acc[nt][3];
                top2_upd(v1a, v2a, i1a, c0, code);
                top2_upd(v1a, v2a, i1a, c1, code + 1);
                top2_upd(v1b, v2b, i1b, c2, code);
                top2_upd(v1b, v2b, i1b, c3, code + 1);
                acc[nt][0] = acc[nt][1] = acc[nt][2] = acc[nt][3] = 0.0f;
            }
        }

        // store next B chunk into the other buffer
        if (g < 63) {
            uint4* dst = (uint4*)(fragB + ((g + 1) & 1) * BSTRIDE);
            dst[t]       = pv0;
            dst[t + 256] = pv1;
        }
        __syncthreads();
    }

    // ---- merge top-2 across the 4 lanes sharing each row ----
    #pragma unroll
    for (int off = 1; off < 4; off <<= 1) {
        float w1 = __shfl_down_sync(0xffffffffu, v1a, off, 4);
        int   wi = __shfl_down_sync(0xffffffffu, i1a, off, 4);
        float w2 = __shfl_down_sync(0xffffffffu, v2a, off, 4);
        if (w1 < v1a || (w1 == v1a && wi < i1a)) {
            v2a = fminf(v1a, w2); v1a = w1; i1a = wi;
        } else v2a = fminf(v2a, w1);
        w1 = __shfl_down_sync(0xffffffffu, v1b, off, 4);
        wi = __shfl_down_sync(0xffffffffu, i1b, off, 4);
        w2 = __shfl_down_sync(0xffffffffu, v2b, off, 4);
        if (w1 < v1b || (w1 == v1b && wi < i1b)) {
            v2b = fminf(v1b, w2); v1b = w1; i1b = wi;
        } else v2b = fminf(v2b, w1);
    }

    const size_t ND = (size_t)N_ROWS * D_DIM;
    if ((lane & 3) == 0) {
        int rA = wid * 16 + (lane >> 2);
        int rB = rA + 8;
        sIdx[rA] = i1a;
        sIdx[rB] = i1b;
        if (v2a - v1a < FLAG_THRESH) {
            int pos = atomicAdd(&d_nflag, 1);
            d_flaglist[pos] = row0 + rA;
        }
        if (v2b - v1b < FLAG_THRESH) {
            int pos = atomicAdd(&d_nflag, 1);
            d_flaglist[pos] = row0 + rB;
        }
        atomicAdd(&d_counts[i1a], 1u);
        atomicAdd(&d_counts[i1b], 1u);
        out[ND + 2 + (size_t)(row0 + rA)] = (float)i1a;
        out[ND + 2 + (size_t)(row0 + rB)] = (float)i1b;
    }
    __syncthreads();

    // ---- quantize (= q exactly) + loss partials ----
    float lsum = 0.0f;
    const float4* inp4 = (const float4*)(inputs + (size_t)row0 * D_DIM);
    float4*       out4 = (float4*)(out + (size_t)row0 * D_DIM);
    const float4* eT4  = (const float4*)d_embedT;
    #pragma unroll 4
    for (int it = 0; it < 32; ++it) {
        int l  = it * 256 + t;
        int r  = l >> 6;
        int d4 = l & 63;
        float4 x = inp4[r * 64 + d4];
        int    k = sIdx[r];
        float4 q = eT4[(size_t)k * 64 + d4];
        float dx = q.x - x.x, dy = q.y - x.y, dz = q.z - x.z, dw = q.w - x.w;
        lsum += dx * dx + dy * dy + dz * dz + dw * dw;
        out4[r * 64 + d4] = q;
    }
    #pragma unroll
    for (int off = 16; off; off >>= 1)
        lsum += __shfl_down_sync(0xffffffffu, lsum, off);
    if ((t & 31) == 0) sRed[t >> 5] = lsum;
    __syncthreads();
    if (t == 0) {
        float s = 0.0f;
        #pragma unroll
        for (int w = 0; w < 8; ++w) s += sRed[w];
        d_loss_partial[blockIdx.x] = s;
    }
}

// ---------------------------------------------------------------------------
// Rescue: re-decide flagged rows with reference-emulated fp32 arithmetic
// ---------------------------------------------------------------------------
__global__ void __launch_bounds__(256)
vq_fix(const float* __restrict__ inputs, float* __restrict__ out) {
    __shared__ float sx[RESCUE_RPB][D_DIM];
    __shared__ float sdist[RESCUE_RPB][K_CODES];
    __shared__ float ssx2[RESCUE_RPB];
    __shared__ int   srow[RESCUE_RPB];
    __shared__ int   sbest[RESCUE_RPB];
    const int t = threadIdx.x;
    const size_t ND = (size_t)N_ROWS * D_DIM;

    const int nf = d_nflag;
    for (int base = blockIdx.x * RESCUE_RPB; base < nf;
         base += gridDim.x * RESCUE_RPB) {
        const int cnt = min(RESCUE_RPB, nf - base);
        __syncthreads();
        if (t < cnt) srow[t] = d_flaglist[base + t];
        __syncthreads();
        for (int r = 0; r < cnt; ++r)
            sx[r][t] = inputs[(size_t)srow[r] * D_DIM + t];
        __syncthreads();
        if (t < cnt) {
            float s = 0.0f;
            for (int d = 0; d < D_DIM; ++d)
                s = __fadd_rn(s, __fmul_rn(sx[t][d], sx[t][d]));
            ssx2[t] = s;
        }
        __syncthreads();

        #pragma unroll
        for (int c = 0; c < 4; ++c) {
            const int k = c * 256 + t;
            const float* e = d_embedT + (size_t)k * D_DIM;
            float acc[RESCUE_RPB];
            #pragma unroll
            for (int r = 0; r < RESCUE_RPB; ++r) acc[r] = 0.0f;
            for (int d = 0; d < D_DIM; ++d) {
                float ev = e[d];
                #pragma unroll
                for (int r = 0; r < RESCUE_RPB; ++r)
                    acc[r] = __fmaf_rn(sx[r][d], ev, acc[r]);
            }
            #pragma unroll
            for (int r = 0; r < RESCUE_RPB; ++r) {
                float twod = __fadd_rn(acc[r], acc[r]);
                float t1   = __fsub_rn(ssx2[r], twod);
                sdist[r][k] = __fadd_rn(t1, d_cnorm[k]);
            }
        }
        __syncthreads();

        if (t < cnt) {
            float best = 3.4e38f; int bk = 0;
            for (int k = 0; k < K_CODES; ++k) {
                float v = sdist[t][k];
                if (v < best) { best = v; bk = k; }
            }
            sbest[t] = bk;
            int oldk = (int)out[ND + 2 + (size_t)srow[t]];
            if (oldk != bk) {
                atomicAdd(&d_counts[bk], 1u);
                atomicAdd(&d_counts[oldk], 0xFFFFFFFFu);
                out[ND + 2 + (size_t)srow[t]] = (float)bk;
            }
        }
        __syncthreads();
        for (int r = 0; r < cnt; ++r)
            out[(size_t)srow[r] * D_DIM + t] =
                d_embedT[(size_t)sbest[r] * D_DIM + t];
    }
}

// ---------------------------------------------------------------------------
// Finalize: loss mean + perplexity
// ---------------------------------------------------------------------------
__global__ void vq_finalize(float* __restrict__ out) {
    __shared__ float sl[1024];
    __shared__ float se[1024];
    int t = threadIdx.x;
    sl[t] = d_loss_partial[t];
    float avg = (float)d_counts[t] * (1.0f / (float)N_ROWS);
    se[t] = avg * logf(avg + 1e-10f);
    __syncthreads();
    for (int s = 512; s; s >>= 1) {
        if (t < s) { sl[t] += sl[t + s]; se[t] += se[t + s]; }
        __syncthreads();
    }
    if (t == 0) {
        const size_t ND = (size_t)N_ROWS * D_DIM;
        out[ND]     = sl[0] / ((float)N_ROWS * (float)D_DIM);
        out[ND + 1] = expf(-se[0]);
    }
}

// ---------------------------------------------------------------------------
extern "C" void kernel_launch(void* const* d_in, const int* in_sizes, int n_in,
                              void* d_out, int out_size) {
    const float* inputs = (const float*)d_in[0];  // [131072, 256]
    const float* embed  = (const float*)d_in[1];  // [256, 1024]
    float* out = (float*)d_out;

    cudaFuncSetAttribute(vq_main_mma,
                         cudaFuncAttributeMaxDynamicSharedMemorySize,
                         SMEM_TOTAL);

    vq_prep<<<8, 128>>>(embed);
    vq_prep_frag<<<64, 256>>>(embed);
    vq_main_mma<<<N_ROWS / 128, 256, SMEM_TOTAL>>>(inputs, out);
    vq_fix<<<256, 256>>>(inputs, out);
    vq_finalize<<<1, 1024>>>(out);
}